// round 5
// baseline (speedup 1.0000x reference)
#include <cuda_runtime.h>
#include <cstdint>

#define BATCH 2
#define NPTS 8192
#define IMGS 64
#define KSEL 8
#define RAD2 0.0025f
#define RADM 0.0501f            // conservative bbox radius
#define NPIX (BATCH * IMGS * IMGS)   // 8192
#define CAP 512                 // per-pixel capacity (hot pixel ~150 expected)
#define GRID 128
#define TPB 256

// Static scratch (allocation-free). BSS-zero at load; phase 2 restores
// g_cnt to zero every launch (graph-replay invariant). g_bar is a
// monotonically increasing generation counter (wrap-safe barrier).
__device__ float4 g_screen[BATCH * NPTS];
__device__ int g_cnt[NPIX];
__device__ unsigned long long g_plist[(size_t)NPIX * CAP];   // 32 MB
__device__ unsigned g_bar;

__global__ __launch_bounds__(TPB) void fused_raster(const float* __restrict__ pts,
                                                    const float* __restrict__ Rm,
                                                    const float* __restrict__ Tv,
                                                    const float* __restrict__ focal,
                                                    float* __restrict__ out) {
    const int gt = blockIdx.x * TPB + threadIdx.x;   // 0..32767

    // ---------------- Phase 1: project + scatter (threads 0..16383) ----------
    if (gt < BATCH * NPTS) {
        const int t = gt;
        const int b = t >> 13;
        const int n = t & (NPTS - 1);
        const float* p = pts + (size_t)t * 3;
        const float* R = Rm + b * 9;
        const float* T = Tv + b * 3;
        float p0 = p[0], p1 = p[1], p2 = p[2];

        float v0 = __fmaf_rn(p2, R[6], __fmaf_rn(p1, R[3], __fmul_rn(p0, R[0])));
        float v1 = __fmaf_rn(p2, R[7], __fmaf_rn(p1, R[4], __fmul_rn(p0, R[1])));
        float v2 = __fmaf_rn(p2, R[8], __fmaf_rn(p1, R[5], __fmul_rn(p0, R[2])));
        v0 = __fadd_rn(v0, T[0]);
        v1 = __fadd_rn(v1, T[1]);
        float z = __fadd_rn(v2, T[2]);

        float x = -__fdiv_rn(__fmul_rn(focal[0], v0), z);
        float y = -__fdiv_rn(__fmul_rn(focal[1], v1), z);
        g_screen[t] = make_float4(x, y, z, 0.0f);

        if (z > 0.0f) {
            // pixel centers c(i) = 1 - (i+0.5)*0.03125, decreasing in i.
            int ix0 = (int)ceilf(__fmul_rn(1.0f - (x + RADM), 32.0f) - 0.5f);
            int ix1 = (int)floorf(__fmul_rn(1.0f - (x - RADM), 32.0f) - 0.5f);
            int iy0 = (int)ceilf(__fmul_rn(1.0f - (y + RADM), 32.0f) - 0.5f);
            int iy1 = (int)floorf(__fmul_rn(1.0f - (y - RADM), 32.0f) - 0.5f);
            ix0 = max(ix0, 0); ix1 = min(ix1, IMGS - 1);
            iy0 = max(iy0, 0); iy1 = min(iy1, IMGS - 1);

            unsigned long long key =
                ((unsigned long long)__float_as_uint(z) << 32) | (unsigned)n;

            // bbox spans at most 4x4 centers (0.1002/0.03125 = 3.2 pitches).
            // Fully unrolled: independent atomic+store pairs pipeline (MLP).
#pragma unroll
            for (int a = 0; a < 4; ++a) {
                int iy = iy0 + a;
                bool vy = iy <= iy1;
                float py = 1.0f - ((float)iy + 0.5f) * 0.03125f;
                float dy = __fsub_rn(py, y);
                float dy2 = __fmul_rn(dy, dy);
#pragma unroll
                for (int c = 0; c < 4; ++c) {
                    int ix = ix0 + c;
                    bool vx = ix <= ix1;
                    float px = 1.0f - ((float)ix + 0.5f) * 0.03125f;
                    float dx = __fsub_rn(px, x);
                    float d2 = __fadd_rn(__fmul_rn(dx, dx), dy2);
                    if (vy && vx && d2 <= RAD2) {   // exact reference predicate
                        int pix = (b << 12) + (iy << 6) + ix;
                        int pos = atomicAdd(&g_cnt[pix], 1);
                        if (pos < CAP)
                            g_plist[(size_t)pix * CAP + pos] = key;
                    }
                }
            }
        }
    }

    // ---------------- Grid barrier (generation counter, no reset needed) -----
    __threadfence();        // make phase-1 writes visible before arrival
    __syncthreads();
    if (threadIdx.x == 0) {
        unsigned gen = atomicAdd(&g_bar, 1u);
        unsigned base = gen & ~(unsigned)(GRID - 1);
        while ((*(volatile unsigned*)&g_bar) - base < (unsigned)GRID) { }
    }
    __syncthreads();
    __threadfence();        // acquire: order list reads after the spin

    // ---------------- Phase 2: thread-per-pixel top-8 select -----------------
    if (gt >= NPIX) return;
    const int pix = gt;
    const int b = pix >> 12;
    const int pp = pix & 4095;
    const float px = 1.0f - ((float)(pp & 63) + 0.5f) * 0.03125f;
    const float py = 1.0f - ((float)(pp >> 6) + 0.5f) * 0.03125f;

    const int cnt = min(g_cnt[pix], CAP);
    const unsigned long long* __restrict__ list = g_plist + (size_t)pix * CAP;

    const unsigned long long SENT = ~0ull;
    unsigned long long key[KSEL];
#pragma unroll
    for (int i = 0; i < KSEL; ++i) key[i] = SENT;

    // Unrolled-by-4 scan for MLP; branchless sorted insert on rare hits.
    int j = 0;
    for (; j + 4 <= cnt; j += 4) {
        unsigned long long k0 = list[j + 0];
        unsigned long long k1 = list[j + 1];
        unsigned long long k2 = list[j + 2];
        unsigned long long k3 = list[j + 3];
#pragma unroll
        for (int q = 0; q < 4; ++q) {
            unsigned long long k = q == 0 ? k0 : q == 1 ? k1 : q == 2 ? k2 : k3;
            if (k < key[KSEL - 1]) {
                unsigned long long v = k;
#pragma unroll
                for (int s2 = 0; s2 < KSEL; ++s2) {
                    unsigned long long cur = key[s2];
                    bool lt = v < cur;
                    key[s2] = lt ? v : cur;
                    v = lt ? cur : v;
                }
            }
        }
    }
    for (; j < cnt; ++j) {
        unsigned long long k = list[j];
        if (k < key[KSEL - 1]) {
            unsigned long long v = k;
#pragma unroll
            for (int s2 = 0; s2 < KSEL; ++s2) {
                unsigned long long cur = key[s2];
                bool lt = v < cur;
                key[s2] = lt ? v : cur;
                v = lt ? cur : v;
            }
        }
    }

    // Emit. key[] is ascending (z, idx) — exactly jax top_k order (unique keys).
    const size_t TSZ = (size_t)NPIX * KSEL;         // 65536
    const size_t o0 = (size_t)pix * KSEL;
#pragma unroll
    for (int r = 0; r < KSEL; ++r) {
        float vi, vz, vd;
        if (key[r] == SENT) {
            vi = -1.0f; vz = -1.0f; vd = -1.0f;
        } else {
            unsigned pidx = (unsigned)key[r];
            float4 s = g_screen[(b << 13) + pidx];
            float dx = __fsub_rn(px, s.x);
            float dy = __fsub_rn(py, s.y);
            vd = __fadd_rn(__fmul_rn(dx, dx), __fmul_rn(dy, dy));
            vz = __uint_as_float((unsigned)(key[r] >> 32));
            vi = (float)pidx;
        }
        out[o0 + r] = vi;
        out[TSZ + o0 + r] = vz;
        out[2 * TSZ + o0 + r] = vd;
    }

    g_cnt[pix] = 0;   // restore zero-state for next graph replay
}

extern "C" void kernel_launch(void* const* d_in, const int* in_sizes, int n_in,
                              void* d_out, int out_size) {
    const float* pts   = (const float*)d_in[0];  // [2,8192,3]
    const float* Rm    = (const float*)d_in[1];  // [2,3,3]
    const float* Tv    = (const float*)d_in[2];  // [2,3]
    const float* focal = (const float*)d_in[3];  // [2]
    float* out = (float*)d_out;

    fused_raster<<<GRID, TPB>>>(pts, Rm, Tv, focal, out);
}

// round 6
// speedup vs baseline: 2.0226x; 2.0226x over previous
#include <cuda_runtime.h>
#include <cstdint>

#define BATCH 2
#define NPTS 8192
#define IMGS 64
#define KSEL 8
#define RAD2 0.0025f
#define RADM 0.0501f            // conservative bbox radius
#define NPIX (BATCH * IMGS * IMGS)   // 8192
#define CAP 512                 // per-pixel capacity (hot pixel ~150 expected)

// Static scratch (allocation-free). BSS-zero at load; select_k restores
// g_cnt to zero every launch (graph-replay invariant).
__device__ float4 g_screen[BATCH * NPTS];
__device__ int g_cnt[NPIX];
__device__ ulonglong2 g_plist[(size_t)NPIX * CAP];   // {key, d2bits} — 64 MB

// ---------------------------------------------------------------------------
// Kernel A: project; scatter exact-test candidates into per-pixel lists.
// Record = (key = zbits<<32|idx, d2bits) so kernel B's fast path never needs
// to gather screen coords. Fixed 4x4 unrolled bbox -> independent atomics.
// ---------------------------------------------------------------------------
__global__ __launch_bounds__(128) void project_scatter(const float* __restrict__ pts,
                                                       const float* __restrict__ Rm,
                                                       const float* __restrict__ Tv,
                                                       const float* __restrict__ focal) {
    int t = blockIdx.x * 128 + threadIdx.x;
    if (t >= BATCH * NPTS) return;
    int b = t >> 13;
    int n = t & (NPTS - 1);
    const float* p = pts + (size_t)t * 3;
    const float* R = Rm + b * 9;
    const float* T = Tv + b * 3;
    float p0 = p[0], p1 = p[1], p2 = p[2];

    float v0 = __fmaf_rn(p2, R[6], __fmaf_rn(p1, R[3], __fmul_rn(p0, R[0])));
    float v1 = __fmaf_rn(p2, R[7], __fmaf_rn(p1, R[4], __fmul_rn(p0, R[1])));
    float v2 = __fmaf_rn(p2, R[8], __fmaf_rn(p1, R[5], __fmul_rn(p0, R[2])));
    v0 = __fadd_rn(v0, T[0]);
    v1 = __fadd_rn(v1, T[1]);
    float z = __fadd_rn(v2, T[2]);

    float x = -__fdiv_rn(__fmul_rn(focal[0], v0), z);
    float y = -__fdiv_rn(__fmul_rn(focal[1], v1), z);
    g_screen[t] = make_float4(x, y, z, 0.0f);   // used only by slow-path emit

    if (!(z > 0.0f)) return;

    // pixel centers c(i) = 1 - (i+0.5)*0.03125, decreasing in i.
    int ix0 = (int)ceilf(__fmul_rn(1.0f - (x + RADM), 32.0f) - 0.5f);
    int ix1 = (int)floorf(__fmul_rn(1.0f - (x - RADM), 32.0f) - 0.5f);
    int iy0 = (int)ceilf(__fmul_rn(1.0f - (y + RADM), 32.0f) - 0.5f);
    int iy1 = (int)floorf(__fmul_rn(1.0f - (y - RADM), 32.0f) - 0.5f);
    ix0 = max(ix0, 0); ix1 = min(ix1, IMGS - 1);
    iy0 = max(iy0, 0); iy1 = min(iy1, IMGS - 1);

    unsigned long long key =
        ((unsigned long long)__float_as_uint(z) << 32) | (unsigned)n;

    // bbox spans at most 4x4 centers (0.1002/0.03125 = 3.2 pitches).
#pragma unroll
    for (int a = 0; a < 4; ++a) {
        int iy = iy0 + a;
        bool vy = iy <= iy1;
        float py = 1.0f - ((float)iy + 0.5f) * 0.03125f;
        float dy = __fsub_rn(py, y);
        float dy2 = __fmul_rn(dy, dy);
#pragma unroll
        for (int c = 0; c < 4; ++c) {
            int ix = ix0 + c;
            bool vx = ix <= ix1;
            float px = 1.0f - ((float)ix + 0.5f) * 0.03125f;
            float dx = __fsub_rn(px, x);
            float d2 = __fadd_rn(__fmul_rn(dx, dx), dy2);
            if (vy && vx && d2 <= RAD2) {       // exact reference predicate
                int pix = (b << 12) + (iy << 6) + ix;
                int pos = atomicAdd(&g_cnt[pix], 1);
                if (pos < CAP)
                    g_plist[(size_t)pix * CAP + pos] =
                        make_ulonglong2(key, (unsigned long long)__float_as_uint(d2));
            }
        }
    }
}

// ---------------------------------------------------------------------------
// Kernel B: one warp per pixel.
//   cnt == 0  : -1 fill.
//   cnt <= 32 : rank selection (independent broadcasts, flat latency),
//               ranked lanes write output slots directly (no gather).
//   cnt  > 32 : per-lane sorted top-8 + 8 rounds warp min+pop (R4 path).
// Keys unique => (z, idx) ascending = jax top_k order exactly.
// ---------------------------------------------------------------------------
__global__ __launch_bounds__(256) void select_k(float* __restrict__ out) {
    const int warp = threadIdx.x >> 5;
    const int lane = threadIdx.x & 31;
    const int pix = blockIdx.x * 8 + warp;          // 0..NPIX-1
    const unsigned long long SENT = ~0ull;
    const size_t TSZ = (size_t)NPIX * KSEL;         // 65536
    const size_t o0 = (size_t)pix * KSEL;

    const ulonglong2* __restrict__ list = g_plist + (size_t)pix * CAP;

    // Overlap the two loads: rec may be garbage (stale/unwritten) — only
    // consumed under lane < cnt.
    int cnt = g_cnt[pix];
    ulonglong2 rec = list[lane];
    cnt = min(cnt, CAP);

    if (cnt == 0) {
        if (lane < KSEL) {
            out[o0 + lane] = -1.0f;
            out[TSZ + o0 + lane] = -1.0f;
            out[2 * TSZ + o0 + lane] = -1.0f;
        }
        return;                                     // g_cnt already 0
    }

    if (cnt <= 32) {
        unsigned long long myk = (lane < cnt) ? rec.x : SENT;
        int rank = 0;
        for (int c = 0; c < cnt; ++c) {             // warp-uniform bound
            unsigned long long kc = __shfl_sync(0xffffffffu, myk, c);
            rank += (kc < myk) ? 1 : 0;
        }
        if (lane < cnt && rank < KSEL) {
            out[o0 + rank] = (float)(unsigned)myk;                         // idx
            out[TSZ + o0 + rank] = __uint_as_float((unsigned)(myk >> 32)); // z
            out[2 * TSZ + o0 + rank] = __uint_as_float((unsigned)rec.y);   // d2
        }
        if (lane >= cnt && lane < KSEL) {           // unfilled slots
            out[o0 + lane] = -1.0f;
            out[TSZ + o0 + lane] = -1.0f;
            out[2 * TSZ + o0 + lane] = -1.0f;
        }
    } else {
        // ---- per-lane sorted top-8 over strided scan (first elem = rec) ----
        unsigned long long key[KSEL];
#pragma unroll
        for (int i = 0; i < KSEL; ++i) key[i] = SENT;
        key[0] = rec.x;                             // j = lane (lane < 32 < cnt)
        for (int j = lane + 32; j < cnt; j += 32) {
            unsigned long long k = list[j].x;
            if (k < key[KSEL - 1]) {
                unsigned long long v = k;
#pragma unroll
                for (int s2 = 0; s2 < KSEL; ++s2) {
                    unsigned long long cur = key[s2];
                    bool lt = v < cur;
                    key[s2] = lt ? v : cur;
                    v = lt ? cur : v;
                }
            }
        }
        // ---- 8 rounds of warp min + pop ----
        unsigned long long mysel = SENT;
#pragma unroll
        for (int r = 0; r < KSEL; ++r) {
            unsigned long long m = key[0];
#pragma unroll
            for (int off = 16; off; off >>= 1) {
                unsigned long long o = __shfl_xor_sync(0xffffffffu, m, off);
                if (o < m) m = o;
            }
            if (m != SENT && key[0] == m) {
#pragma unroll
                for (int s2 = 0; s2 < KSEL - 1; ++s2) key[s2] = key[s2 + 1];
                key[KSEL - 1] = SENT;
            }
            if (lane == r) mysel = m;
        }
        if (lane < KSEL) {
            const int b = pix >> 12;
            const int pp = pix & 4095;
            const float px = 1.0f - ((float)(pp & 63) + 0.5f) * 0.03125f;
            const float py = 1.0f - ((float)(pp >> 6) + 0.5f) * 0.03125f;
            float vi, vz, vd;
            if (mysel == SENT) {
                vi = -1.0f; vz = -1.0f; vd = -1.0f;
            } else {
                unsigned pidx = (unsigned)mysel;
                float4 s = g_screen[(b << 13) + pidx];
                float dx = __fsub_rn(px, s.x);
                float dy = __fsub_rn(py, s.y);
                vd = __fadd_rn(__fmul_rn(dx, dx), __fmul_rn(dy, dy));
                vz = __uint_as_float((unsigned)(mysel >> 32));
                vi = (float)pidx;
            }
            out[o0 + lane] = vi;
            out[TSZ + o0 + lane] = vz;
            out[2 * TSZ + o0 + lane] = vd;
        }
    }

    if (lane == 0) g_cnt[pix] = 0;   // restore zero-state for next replay
}

extern "C" void kernel_launch(void* const* d_in, const int* in_sizes, int n_in,
                              void* d_out, int out_size) {
    const float* pts   = (const float*)d_in[0];  // [2,8192,3]
    const float* Rm    = (const float*)d_in[1];  // [2,3,3]
    const float* Tv    = (const float*)d_in[2];  // [2,3]
    const float* focal = (const float*)d_in[3];  // [2]
    float* out = (float*)d_out;

    project_scatter<<<(BATCH * NPTS + 127) / 128, 128>>>(pts, Rm, Tv, focal);
    select_k<<<NPIX / 8, 256>>>(out);
}

// round 7
// speedup vs baseline: 2.2241x; 1.0996x over previous
#include <cuda_runtime.h>
#include <cstdint>

#define BATCH 2
#define NPTS 8192
#define IMGS 64
#define KSEL 8
#define RAD2 0.0025f
#define RADM 0.0501f            // conservative bbox radius
#define NPIX (BATCH * IMGS * IMGS)   // 8192
#define CAP 512                 // per-pixel capacity (hot pixel ~150 expected)

// Static scratch (allocation-free). BSS-zero at load; select_k restores
// g_cnt to zero every launch (graph-replay invariant).
__device__ float4 g_screen[BATCH * NPTS];
__device__ int g_cnt[NPIX];
__device__ unsigned long long g_keys[(size_t)NPIX * CAP];  // zbits<<32|idx, 32MB
__device__ float g_d2[(size_t)NPIX * CAP];                 // 16MB

// ---------------------------------------------------------------------------
// Kernel A: project + scatter. FOUR lanes per point: each lane redundantly
// projects (loads broadcast-coalesce, ALU is cheap) and owns one bbox ROW
// (4 predicated atomic+store pairs). 65536 threads -> ~4x the warps of the
// old layout, hiding the ~318-cycle ATOMG chains.
// ---------------------------------------------------------------------------
__global__ __launch_bounds__(256) void project_scatter(const float* __restrict__ pts,
                                                       const float* __restrict__ Rm,
                                                       const float* __restrict__ Tv,
                                                       const float* __restrict__ focal) {
    const int gt = blockIdx.x * 256 + threadIdx.x;   // 0..65535
    const int t = gt >> 2;                           // point id 0..16383
    const int row = gt & 3;                          // bbox row this lane owns
    const int b = t >> 13;
    const int n = t & (NPTS - 1);
    const float* p = pts + (size_t)t * 3;
    const float* R = Rm + b * 9;
    const float* T = Tv + b * 3;
    float p0 = p[0], p1 = p[1], p2 = p[2];

    float v0 = __fmaf_rn(p2, R[6], __fmaf_rn(p1, R[3], __fmul_rn(p0, R[0])));
    float v1 = __fmaf_rn(p2, R[7], __fmaf_rn(p1, R[4], __fmul_rn(p0, R[1])));
    float v2 = __fmaf_rn(p2, R[8], __fmaf_rn(p1, R[5], __fmul_rn(p0, R[2])));
    v0 = __fadd_rn(v0, T[0]);
    v1 = __fadd_rn(v1, T[1]);
    float z = __fadd_rn(v2, T[2]);

    float x = -__fdiv_rn(__fmul_rn(focal[0], v0), z);
    float y = -__fdiv_rn(__fmul_rn(focal[1], v1), z);
    if (row == 0) g_screen[t] = make_float4(x, y, z, 0.0f);  // slow-path emit data

    if (!(z > 0.0f)) return;

    // pixel centers c(i) = 1 - (i+0.5)*0.03125, decreasing in i.
    int ix0 = (int)ceilf(__fmul_rn(1.0f - (x + RADM), 32.0f) - 0.5f);
    int ix1 = (int)floorf(__fmul_rn(1.0f - (x - RADM), 32.0f) - 0.5f);
    int iy0 = (int)ceilf(__fmul_rn(1.0f - (y + RADM), 32.0f) - 0.5f);
    int iy1 = (int)floorf(__fmul_rn(1.0f - (y - RADM), 32.0f) - 0.5f);
    ix0 = max(ix0, 0); ix1 = min(ix1, IMGS - 1);
    iy0 = max(iy0, 0); iy1 = min(iy1, IMGS - 1);

    // bbox spans at most 4x4 centers; this lane handles row iy0+row.
    const int iy = iy0 + row;
    if (iy > iy1) return;

    const unsigned long long key =
        ((unsigned long long)__float_as_uint(z) << 32) | (unsigned)n;

    float py = 1.0f - ((float)iy + 0.5f) * 0.03125f;
    float dy = __fsub_rn(py, y);
    float dy2 = __fmul_rn(dy, dy);
#pragma unroll
    for (int c = 0; c < 4; ++c) {
        int ix = ix0 + c;
        bool vx = ix <= ix1;
        float px = 1.0f - ((float)ix + 0.5f) * 0.03125f;
        float dx = __fsub_rn(px, x);
        float d2 = __fadd_rn(__fmul_rn(dx, dx), dy2);
        if (vx && d2 <= RAD2) {                 // exact reference predicate
            int pix = (b << 12) + (iy << 6) + ix;
            int pos = atomicAdd(&g_cnt[pix], 1);
            if (pos < CAP) {
                g_keys[(size_t)pix * CAP + pos] = key;
                g_d2[(size_t)pix * CAP + pos] = d2;
            }
        }
    }
}

// ---------------------------------------------------------------------------
// Kernel B: one warp per pixel.
//   cnt == 0   : -1 fill.
//   cnt <= 32  : rank selection, 1 key/lane (flat latency, no chains).
//   cnt <= 64  : rank selection, 2 keys/lane.
//   cnt  > 64  : per-lane sorted top-8 + 8 rounds warp min+pop.
// Keys unique => (z, idx) ascending = jax top_k order exactly.
// ---------------------------------------------------------------------------
__global__ __launch_bounds__(256) void select_k(float* __restrict__ out) {
    const int warp = threadIdx.x >> 5;
    const int lane = threadIdx.x & 31;
    const int pix = blockIdx.x * 8 + warp;          // 0..NPIX-1
    const unsigned long long SENT = ~0ull;
    const size_t TSZ = (size_t)NPIX * KSEL;         // 65536
    const size_t o0 = (size_t)pix * KSEL;

    const unsigned long long* __restrict__ keys = g_keys + (size_t)pix * CAP;
    const float* __restrict__ d2s = g_d2 + (size_t)pix * CAP;

    // Overlap loads; k0/d0 only consumed under lane < cnt.
    int cnt = g_cnt[pix];
    unsigned long long k0 = keys[lane];
    float d0 = d2s[lane];
    cnt = min(cnt, CAP);

    if (cnt == 0) {
        if (lane < KSEL) {
            out[o0 + lane] = -1.0f;
            out[TSZ + o0 + lane] = -1.0f;
            out[2 * TSZ + o0 + lane] = -1.0f;
        }
        return;                                     // g_cnt already 0
    }

    if (cnt <= 64) {
        // ---- rank selection, up to 2 keys per lane ----
        unsigned long long k1 = SENT;
        float d1 = 0.0f;
        if (cnt > 32) {                             // warp-uniform branch
            if (lane + 32 < cnt) { k1 = keys[lane + 32]; d1 = d2s[lane + 32]; }
        }
        if (lane >= cnt) k0 = SENT;

        int r0 = 0, r1 = 0;
        const int c1 = min(cnt, 32);
        for (int c = 0; c < c1; ++c) {              // independent broadcasts
            unsigned long long kc = __shfl_sync(0xffffffffu, k0, c);
            r0 += (kc < k0) ? 1 : 0;
            r1 += (kc < k1) ? 1 : 0;
        }
        for (int c = 32; c < cnt; ++c) {
            unsigned long long kc = __shfl_sync(0xffffffffu, k1, c - 32);
            r0 += (kc < k0) ? 1 : 0;
            r1 += (kc < k1) ? 1 : 0;
        }
        if (lane < cnt && r0 < KSEL) {
            out[o0 + r0] = (float)(unsigned)k0;
            out[TSZ + o0 + r0] = __uint_as_float((unsigned)(k0 >> 32));
            out[2 * TSZ + o0 + r0] = d0;
        }
        if (lane + 32 < cnt && r1 < KSEL) {
            out[o0 + r1] = (float)(unsigned)k1;
            out[TSZ + o0 + r1] = __uint_as_float((unsigned)(k1 >> 32));
            out[2 * TSZ + o0 + r1] = d1;
        }
        if (lane >= cnt && lane < KSEL) {           // unfilled slots (cnt < 8)
            out[o0 + lane] = -1.0f;
            out[TSZ + o0 + lane] = -1.0f;
            out[2 * TSZ + o0 + lane] = -1.0f;
        }
    } else {
        // ---- per-lane sorted top-8 over strided scan ----
        unsigned long long key[KSEL];
#pragma unroll
        for (int i = 0; i < KSEL; ++i) key[i] = SENT;
        key[0] = k0;                                // element `lane` (< cnt)
        for (int j = lane + 32; j < cnt; j += 32) {
            unsigned long long k = keys[j];
            if (k < key[KSEL - 1]) {
                unsigned long long v = k;
#pragma unroll
                for (int s2 = 0; s2 < KSEL; ++s2) {
                    unsigned long long cur = key[s2];
                    bool lt = v < cur;
                    key[s2] = lt ? v : cur;
                    v = lt ? cur : v;
                }
            }
        }
        // ---- 8 rounds of warp min + pop (unique keys => one pop/round) ----
        unsigned long long mysel = SENT;
#pragma unroll
        for (int r = 0; r < KSEL; ++r) {
            unsigned long long m = key[0];
#pragma unroll
            for (int off = 16; off; off >>= 1) {
                unsigned long long o = __shfl_xor_sync(0xffffffffu, m, off);
                if (o < m) m = o;
            }
            if (m != SENT && key[0] == m) {
#pragma unroll
                for (int s2 = 0; s2 < KSEL - 1; ++s2) key[s2] = key[s2 + 1];
                key[KSEL - 1] = SENT;
            }
            if (lane == r) mysel = m;
        }
        if (lane < KSEL) {
            const int b = pix >> 12;
            const int pp = pix & 4095;
            const float px = 1.0f - ((float)(pp & 63) + 0.5f) * 0.03125f;
            const float py = 1.0f - ((float)(pp >> 6) + 0.5f) * 0.03125f;
            float vi, vz, vd;
            if (mysel == SENT) {
                vi = -1.0f; vz = -1.0f; vd = -1.0f;
            } else {
                unsigned pidx = (unsigned)mysel;
                float4 s = g_screen[(b << 13) + pidx];
                float dx = __fsub_rn(px, s.x);
                float dy = __fsub_rn(py, s.y);
                vd = __fadd_rn(__fmul_rn(dx, dx), __fmul_rn(dy, dy));
                vz = __uint_as_float((unsigned)(mysel >> 32));
                vi = (float)pidx;
            }
            out[o0 + lane] = vi;
            out[TSZ + o0 + lane] = vz;
            out[2 * TSZ + o0 + lane] = vd;
        }
    }

    if (lane == 0) g_cnt[pix] = 0;   // restore zero-state for next replay
}

extern "C" void kernel_launch(void* const* d_in, const int* in_sizes, int n_in,
                              void* d_out, int out_size) {
    const float* pts   = (const float*)d_in[0];  // [2,8192,3]
    const float* Rm    = (const float*)d_in[1];  // [2,3,3]
    const float* Tv    = (const float*)d_in[2];  // [2,3]
    const float* focal = (const float*)d_in[3];  // [2]
    float* out = (float*)d_out;

    project_scatter<<<BATCH * NPTS * 4 / 256, 256>>>(pts, Rm, Tv, focal);
    select_k<<<NPIX / 8, 256>>>(out);
}

// round 8
// speedup vs baseline: 2.4650x; 1.1083x over previous
#include <cuda_runtime.h>
#include <cstdint>

#define BATCH 2
#define NPTS 8192
#define IMGS 64
#define KSEL 8
#define RAD2 0.0025f
#define RADM 0.0501f            // conservative bbox radius
#define NPIX (BATCH * IMGS * IMGS)   // 8192
#define CAP 256                 // per-pixel capacity (hot pixel ~150; +13 sigma)

// Static scratch (allocation-free). BSS-zero at load; select_k restores
// g_cnt to zero every launch (graph-replay invariant).
__device__ float4 g_screen[BATCH * NPTS];
__device__ int g_cnt[NPIX];
__device__ ulonglong2 g_plist[(size_t)NPIX * CAP];   // {key, d2bits} — 32 MB

// ---------------------------------------------------------------------------
// Kernel A: project + scatter. EIGHT lanes per point: each lane redundantly
// projects (broadcast-coalesced loads, cheap ALU) and owns a 1x2 sub-row of
// the 4x4 bbox (<=2 independent atomic+store pairs). 131072 threads hide the
// ~318-cycle ATOMG latency.
// ---------------------------------------------------------------------------
__global__ __launch_bounds__(256) void project_scatter(const float* __restrict__ pts,
                                                       const float* __restrict__ Rm,
                                                       const float* __restrict__ Tv,
                                                       const float* __restrict__ focal) {
    const int gt = blockIdx.x * 256 + threadIdx.x;   // 0..131071
    const int t = gt >> 3;                           // point id 0..16383
    const int sub = gt & 7;
    const int row = sub >> 1;                        // bbox row 0..3
    const int ch = (sub & 1) << 1;                   // bbox col pair: 0 or 2
    const int b = t >> 13;
    const int n = t & (NPTS - 1);
    const float* p = pts + (size_t)t * 3;
    const float* R = Rm + b * 9;
    const float* T = Tv + b * 3;
    float p0 = p[0], p1 = p[1], p2 = p[2];

    float v0 = __fmaf_rn(p2, R[6], __fmaf_rn(p1, R[3], __fmul_rn(p0, R[0])));
    float v1 = __fmaf_rn(p2, R[7], __fmaf_rn(p1, R[4], __fmul_rn(p0, R[1])));
    float v2 = __fmaf_rn(p2, R[8], __fmaf_rn(p1, R[5], __fmul_rn(p0, R[2])));
    v0 = __fadd_rn(v0, T[0]);
    v1 = __fadd_rn(v1, T[1]);
    float z = __fadd_rn(v2, T[2]);

    float x = -__fdiv_rn(__fmul_rn(focal[0], v0), z);
    float y = -__fdiv_rn(__fmul_rn(focal[1], v1), z);
    if (sub == 0) g_screen[t] = make_float4(x, y, z, 0.0f);  // slow-path emit data

    if (!(z > 0.0f)) return;

    // pixel centers c(i) = 1 - (i+0.5)*0.03125, decreasing in i.
    int ix0 = (int)ceilf(__fmul_rn(1.0f - (x + RADM), 32.0f) - 0.5f);
    int ix1 = (int)floorf(__fmul_rn(1.0f - (x - RADM), 32.0f) - 0.5f);
    int iy0 = (int)ceilf(__fmul_rn(1.0f - (y + RADM), 32.0f) - 0.5f);
    int iy1 = (int)floorf(__fmul_rn(1.0f - (y - RADM), 32.0f) - 0.5f);
    ix0 = max(ix0, 0); ix1 = min(ix1, IMGS - 1);
    iy0 = max(iy0, 0); iy1 = min(iy1, IMGS - 1);

    // bbox spans at most 4x4 centers; this lane: row iy0+row, cols ix0+ch..+1.
    const int iy = iy0 + row;
    if (iy > iy1) return;

    const unsigned long long key =
        ((unsigned long long)__float_as_uint(z) << 32) | (unsigned)n;

    float py = 1.0f - ((float)iy + 0.5f) * 0.03125f;
    float dy = __fsub_rn(py, y);
    float dy2 = __fmul_rn(dy, dy);
#pragma unroll
    for (int c = 0; c < 2; ++c) {
        int ix = ix0 + ch + c;
        bool vx = ix <= ix1;
        float px = 1.0f - ((float)ix + 0.5f) * 0.03125f;
        float dx = __fsub_rn(px, x);
        float d2 = __fadd_rn(__fmul_rn(dx, dx), dy2);
        if (vx && d2 <= RAD2) {                 // exact reference predicate
            int pix = (b << 12) + (iy << 6) + ix;
            int pos = atomicAdd(&g_cnt[pix], 1);
            if (pos < CAP)
                g_plist[(size_t)pix * CAP + pos] =
                    make_ulonglong2(key, (unsigned long long)__float_as_uint(d2));
        }
    }
}

// ---------------------------------------------------------------------------
// Kernel B: one warp per pixel.
//   cnt == 0   : -1 fill.
//   cnt <= 32  : rank selection, 1 key/lane (exact R6 hot path).
//   cnt <= 64  : rank selection, 2 keys/lane (2nd record loaded in-tier).
//   cnt  > 64  : per-lane sorted top-8 + 8 rounds warp min+pop.
// Keys unique => (z, idx) ascending = jax top_k order exactly.
// ---------------------------------------------------------------------------
__global__ __launch_bounds__(256) void select_k(float* __restrict__ out) {
    const int warp = threadIdx.x >> 5;
    const int lane = threadIdx.x & 31;
    const int pix = blockIdx.x * 8 + warp;          // 0..NPIX-1
    const unsigned long long SENT = ~0ull;
    const size_t TSZ = (size_t)NPIX * KSEL;         // 65536
    const size_t o0 = (size_t)pix * KSEL;

    const ulonglong2* __restrict__ list = g_plist + (size_t)pix * CAP;

    // Overlap the two loads; rec only consumed under lane < cnt.
    int cnt = g_cnt[pix];
    ulonglong2 rec = list[lane];
    cnt = min(cnt, CAP);

    if (cnt == 0) {
        if (lane < KSEL) {
            out[o0 + lane] = -1.0f;
            out[TSZ + o0 + lane] = -1.0f;
            out[2 * TSZ + o0 + lane] = -1.0f;
        }
        return;                                     // g_cnt already 0
    }

    if (cnt <= 32) {
        // ---- exact R6 hot path: single-key rank selection ----
        unsigned long long myk = (lane < cnt) ? rec.x : SENT;
        int rank = 0;
        for (int c = 0; c < cnt; ++c) {             // warp-uniform bound
            unsigned long long kc = __shfl_sync(0xffffffffu, myk, c);
            rank += (kc < myk) ? 1 : 0;
        }
        if (lane < cnt && rank < KSEL) {
            out[o0 + rank] = (float)(unsigned)myk;                         // idx
            out[TSZ + o0 + rank] = __uint_as_float((unsigned)(myk >> 32)); // z
            out[2 * TSZ + o0 + rank] = __uint_as_float((unsigned)rec.y);   // d2
        }
        if (lane >= cnt && lane < KSEL) {           // unfilled slots
            out[o0 + lane] = -1.0f;
            out[TSZ + o0 + lane] = -1.0f;
            out[2 * TSZ + o0 + lane] = -1.0f;
        }
    } else if (cnt <= 64) {
        // ---- two-key rank selection (all tier costs paid inside the tier) --
        unsigned long long k0 = rec.x;              // lane < 32 < cnt: valid
        unsigned long long k1 = SENT;
        unsigned d1bits = 0;
        if (lane + 32 < cnt) {
            ulonglong2 rec2 = list[lane + 32];
            k1 = rec2.x;
            d1bits = (unsigned)rec2.y;
        }
        int r0 = 0, r1 = 0;
#pragma unroll 4
        for (int c = 0; c < 32; ++c) {
            unsigned long long kc = __shfl_sync(0xffffffffu, k0, c);
            r0 += (kc < k0) ? 1 : 0;
            r1 += (kc < k1) ? 1 : 0;
        }
        for (int c = 32; c < cnt; ++c) {
            unsigned long long kc = __shfl_sync(0xffffffffu, k1, c - 32);
            r0 += (kc < k0) ? 1 : 0;
            r1 += (kc < k1) ? 1 : 0;
        }
        // cnt > 8 => ranks 0..7 all occupied; no fill needed.
        if (r0 < KSEL) {
            out[o0 + r0] = (float)(unsigned)k0;
            out[TSZ + o0 + r0] = __uint_as_float((unsigned)(k0 >> 32));
            out[2 * TSZ + o0 + r0] = __uint_as_float((unsigned)rec.y);
        }
        if (lane + 32 < cnt && r1 < KSEL) {
            out[o0 + r1] = (float)(unsigned)k1;
            out[TSZ + o0 + r1] = __uint_as_float((unsigned)(k1 >> 32));
            out[2 * TSZ + o0 + r1] = __uint_as_float(d1bits);
        }
    } else {
        // ---- per-lane sorted top-8 over strided scan ----
        unsigned long long key[KSEL];
#pragma unroll
        for (int i = 0; i < KSEL; ++i) key[i] = SENT;
        key[0] = rec.x;                             // element `lane` (< cnt)
        for (int j = lane + 32; j < cnt; j += 32) {
            unsigned long long k = list[j].x;
            if (k < key[KSEL - 1]) {
                unsigned long long v = k;
#pragma unroll
                for (int s2 = 0; s2 < KSEL; ++s2) {
                    unsigned long long cur = key[s2];
                    bool lt = v < cur;
                    key[s2] = lt ? v : cur;
                    v = lt ? cur : v;
                }
            }
        }
        // ---- 8 rounds of warp min + pop (unique keys => one pop/round) ----
        unsigned long long mysel = SENT;
#pragma unroll
        for (int r = 0; r < KSEL; ++r) {
            unsigned long long m = key[0];
#pragma unroll
            for (int off = 16; off; off >>= 1) {
                unsigned long long o = __shfl_xor_sync(0xffffffffu, m, off);
                if (o < m) m = o;
            }
            if (m != SENT && key[0] == m) {
#pragma unroll
                for (int s2 = 0; s2 < KSEL - 1; ++s2) key[s2] = key[s2 + 1];
                key[KSEL - 1] = SENT;
            }
            if (lane == r) mysel = m;
        }
        if (lane < KSEL) {
            const int b = pix >> 12;
            const int pp = pix & 4095;
            const float px = 1.0f - ((float)(pp & 63) + 0.5f) * 0.03125f;
            const float py = 1.0f - ((float)(pp >> 6) + 0.5f) * 0.03125f;
            float vi, vz, vd;
            if (mysel == SENT) {
                vi = -1.0f; vz = -1.0f; vd = -1.0f;
            } else {
                unsigned pidx = (unsigned)mysel;
                float4 s = g_screen[(b << 13) + pidx];
                float dx = __fsub_rn(px, s.x);
                float dy = __fsub_rn(py, s.y);
                vd = __fadd_rn(__fmul_rn(dx, dx), __fmul_rn(dy, dy));
                vz = __uint_as_float((unsigned)(mysel >> 32));
                vi = (float)pidx;
            }
            out[o0 + lane] = vi;
            out[TSZ + o0 + lane] = vz;
            out[2 * TSZ + o0 + lane] = vd;
        }
    }

    if (lane == 0) g_cnt[pix] = 0;   // restore zero-state for next replay
}

extern "C" void kernel_launch(void* const* d_in, const int* in_sizes, int n_in,
                              void* d_out, int out_size) {
    const float* pts   = (const float*)d_in[0];  // [2,8192,3]
    const float* Rm    = (const float*)d_in[1];  // [2,3,3]
    const float* Tv    = (const float*)d_in[2];  // [2,3]
    const float* focal = (const float*)d_in[3];  // [2]
    float* out = (float*)d_out;

    project_scatter<<<BATCH * NPTS * 8 / 256, 256>>>(pts, Rm, Tv, focal);
    select_k<<<NPIX / 8, 256>>>(out);
}